// round 1
// baseline (speedup 1.0000x reference)
#include <cuda_runtime.h>
#include <math.h>

#define BB 2
#define LL 2048
#define DD 1024
#define HH 16
#define DHH 64

// Scratch (allocation-free rule: __device__ globals)
__device__ float g_q[BB * LL * DD];
__device__ float g_k[BB * LL * DD];
__device__ float g_v[BB * LL * DD];
__device__ float g_ao[BB * LL * DD];

// ---------------------------------------------------------------------------
// SGEMM: C[M,N] = A[M,K] @ W[K,N] + bias[N]
// M = 4096, N = K = 1024. BM=BN=128, BK=16, 256 threads, 8x8 per thread.
// ---------------------------------------------------------------------------
__device__ __forceinline__ void gemm_body(const float* __restrict__ A,
                                          const float* __restrict__ W,
                                          const float* __restrict__ bias,
                                          float* __restrict__ C)
{
    const int M = BB * LL;
    const int N = DD;
    const int K = DD;

    __shared__ __align__(16) float As[16][128];  // [k][m]
    __shared__ __align__(16) float Ws[16][128];  // [k][n]

    const int tid = threadIdx.x;
    const int m0 = blockIdx.y * 128;
    const int n0 = blockIdx.x * 128;
    const int ty = tid >> 4;   // 0..15
    const int tx = tid & 15;   // 0..15

    float acc[8][8];
#pragma unroll
    for (int i = 0; i < 8; i++)
#pragma unroll
        for (int j = 0; j < 8; j++) acc[i][j] = 0.f;

    for (int k0 = 0; k0 < K; k0 += 16) {
#pragma unroll
        for (int it = 0; it < 2; it++) {
            int idx = tid + (it << 8);         // 0..511
            // A tile: 128 rows x 16 k, float4 along k, store transposed
            int r  = idx >> 2;                 // 0..127
            int kq = (idx & 3) << 2;           // 0,4,8,12
            float4 av = *(const float4*)(A + (size_t)(m0 + r) * K + (k0 + kq));
            As[kq + 0][r] = av.x;
            As[kq + 1][r] = av.y;
            As[kq + 2][r] = av.z;
            As[kq + 3][r] = av.w;
            // W tile: 16 rows x 128 n, float4 along n
            int kr = idx >> 5;                 // 0..15
            int nc = (idx & 31) << 2;          // 0..124
            *(float4*)(&Ws[kr][nc]) =
                *(const float4*)(W + (size_t)(k0 + kr) * N + (n0 + nc));
        }
        __syncthreads();

#pragma unroll
        for (int kk = 0; kk < 16; kk++) {
            float a[8], b[8];
            *(float4*)&a[0] = *(const float4*)&As[kk][ty * 8];
            *(float4*)&a[4] = *(const float4*)&As[kk][ty * 8 + 4];
            *(float4*)&b[0] = *(const float4*)&Ws[kk][tx * 8];
            *(float4*)&b[4] = *(const float4*)&Ws[kk][tx * 8 + 4];
#pragma unroll
            for (int i = 0; i < 8; i++)
#pragma unroll
                for (int j = 0; j < 8; j++)
                    acc[i][j] = fmaf(a[i], b[j], acc[i][j]);
        }
        __syncthreads();
    }

#pragma unroll
    for (int i = 0; i < 8; i++) {
        int m = m0 + ty * 8 + i;
#pragma unroll
        for (int j = 0; j < 8; j += 4) {
            int n = n0 + tx * 8 + j;
            float4 ov;
            ov.x = acc[i][j + 0] + bias[n + 0];
            ov.y = acc[i][j + 1] + bias[n + 1];
            ov.z = acc[i][j + 2] + bias[n + 2];
            ov.w = acc[i][j + 3] + bias[n + 3];
            *(float4*)(C + (size_t)m * N + n) = ov;
        }
    }
}

__global__ __launch_bounds__(256) void sgemm_qkv(const float* __restrict__ x,
                                                 const float* __restrict__ wq,
                                                 const float* __restrict__ bq,
                                                 const float* __restrict__ wk,
                                                 const float* __restrict__ bk,
                                                 const float* __restrict__ wv,
                                                 const float* __restrict__ bv)
{
    const float* W;
    const float* bias;
    float* C;
    if (blockIdx.z == 0)      { W = wq; bias = bq; C = g_q; }
    else if (blockIdx.z == 1) { W = wk; bias = bk; C = g_k; }
    else                      { W = wv; bias = bv; C = g_v; }
    gemm_body(x, W, bias, C);
}

__global__ __launch_bounds__(256) void sgemm_out(const float* __restrict__ W,
                                                 const float* __restrict__ bias,
                                                 float* __restrict__ C)
{
    gemm_body(g_ao, W, bias, C);
}

// ---------------------------------------------------------------------------
// Flash attention, fp32, causal. One block per (b, h, 64-query tile).
// 256 threads; 4x4 register micro-tiles for both S=QK^T and O+=PV.
// Smem: Qt[64][64] (d-major), KtPs[64][64] (K tile d-major, reused as P tile
// row-major), Vs[64][64] (key-major). Total 48 KB static.
// ---------------------------------------------------------------------------
__global__ __launch_bounds__(256) void attn_kernel()
{
    __shared__ __align__(16) float Qt[64 * 64];    // Qt[d*64 + row], pre-scaled
    __shared__ __align__(16) float KtPs[64 * 64];  // Kt[d*64 + key] then Ps[row*64 + key]
    __shared__ __align__(16) float Vs[64 * 64];    // Vs[key*64 + d]

    const int tid = threadIdx.x;
    const int bh = blockIdx.y;          // 0..31
    const int b = bh >> 4;
    const int h = bh & 15;
    const int q0 = blockIdx.x << 6;

    const float* qp = g_q + ((size_t)(b * LL + q0)) * DD + h * DHH;
    const float* kp = g_k + ((size_t)(b * LL)) * DD + h * DHH;
    const float* vp = g_v + ((size_t)(b * LL)) * DD + h * DHH;

    // Load Q tile transposed + scaled by 1/sqrt(Dh) = 0.125
#pragma unroll
    for (int it = 0; it < 4; it++) {
        int idx = tid + (it << 8);      // 0..1023
        int r = idx >> 4;               // 0..63
        int c = (idx & 15) << 2;        // 0..60
        float4 t = *(const float4*)(qp + (size_t)r * DD + c);
        Qt[(c + 0) * 64 + r] = t.x * 0.125f;
        Qt[(c + 1) * 64 + r] = t.y * 0.125f;
        Qt[(c + 2) * 64 + r] = t.z * 0.125f;
        Qt[(c + 3) * 64 + r] = t.w * 0.125f;
    }

    const int rg = tid >> 4;            // row group: rows rg*4..+3
    const int cg = tid & 15;            // col group: cols cg*4..+3
    const int r0 = rg << 2;
    const int c0 = cg << 2;

    float m_r[4], l_r[4], o[4][4];
#pragma unroll
    for (int i = 0; i < 4; i++) {
        m_r[i] = -1e30f;
        l_r[i] = 0.f;
#pragma unroll
        for (int j = 0; j < 4; j++) o[i][j] = 0.f;
    }

    const int ntiles = (q0 >> 6) + 1;   // causal: kv tiles 0..q0/64
    for (int t = 0; t < ntiles; t++) {
        const int k0 = t << 6;
        __syncthreads();  // prev O-phase done (also covers Q load on t=0)

        // Load K (transposed, d-major) and V (key-major)
#pragma unroll
        for (int it = 0; it < 4; it++) {
            int idx = tid + (it << 8);
            int r = idx >> 4;
            int c = (idx & 15) << 2;
            float4 kv = *(const float4*)(kp + (size_t)(k0 + r) * DD + c);
            KtPs[(c + 0) * 64 + r] = kv.x;
            KtPs[(c + 1) * 64 + r] = kv.y;
            KtPs[(c + 2) * 64 + r] = kv.z;
            KtPs[(c + 3) * 64 + r] = kv.w;
            *(float4*)(Vs + r * 64 + c) =
                *(const float4*)(vp + (size_t)(k0 + r) * DD + c);
        }
        __syncthreads();

        // S = Q K^T, 4x4 micro-tile
        float s[4][4];
#pragma unroll
        for (int i = 0; i < 4; i++)
#pragma unroll
            for (int j = 0; j < 4; j++) s[i][j] = 0.f;

#pragma unroll
        for (int d = 0; d < 64; d++) {
            float a[4], bb[4];
            *(float4*)a  = *(const float4*)(Qt + d * 64 + r0);
            *(float4*)bb = *(const float4*)(KtPs + d * 64 + c0);
#pragma unroll
            for (int i = 0; i < 4; i++)
#pragma unroll
                for (int j = 0; j < 4; j++)
                    s[i][j] = fmaf(a[i], bb[j], s[i][j]);
        }

        // Causal mask: only the diagonal tile is partially masked
        if (k0 == q0) {
#pragma unroll
            for (int i = 0; i < 4; i++)
#pragma unroll
                for (int j = 0; j < 4; j++)
                    if (c0 + j > r0 + i) s[i][j] = -1e30f;
        }

        // Online softmax (row stats via 16-lane shfl groups)
#pragma unroll
        for (int i = 0; i < 4; i++) {
            float mx = fmaxf(fmaxf(s[i][0], s[i][1]), fmaxf(s[i][2], s[i][3]));
            mx = fmaxf(mx, __shfl_xor_sync(0xffffffffu, mx, 1));
            mx = fmaxf(mx, __shfl_xor_sync(0xffffffffu, mx, 2));
            mx = fmaxf(mx, __shfl_xor_sync(0xffffffffu, mx, 4));
            mx = fmaxf(mx, __shfl_xor_sync(0xffffffffu, mx, 8));
            float m_new = fmaxf(m_r[i], mx);
            float alpha = __expf(m_r[i] - m_new);
            m_r[i] = m_new;
            float rs = 0.f;
#pragma unroll
            for (int j = 0; j < 4; j++) {
                float p = __expf(s[i][j] - m_new);
                s[i][j] = p;
                rs += p;
            }
            rs += __shfl_xor_sync(0xffffffffu, rs, 1);
            rs += __shfl_xor_sync(0xffffffffu, rs, 2);
            rs += __shfl_xor_sync(0xffffffffu, rs, 4);
            rs += __shfl_xor_sync(0xffffffffu, rs, 8);
            l_r[i] = l_r[i] * alpha + rs;
#pragma unroll
            for (int j = 0; j < 4; j++) o[i][j] *= alpha;
        }

        __syncthreads();  // everyone done reading Kt before P overwrites it
#pragma unroll
        for (int i = 0; i < 4; i++)
            *(float4*)(KtPs + (r0 + i) * 64 + c0) =
                make_float4(s[i][0], s[i][1], s[i][2], s[i][3]);
        __syncthreads();

        // O += P @ V, 4x4 micro-tile over keys (16 blocks of 4)
#pragma unroll
        for (int jb = 0; jb < 16; jb++) {
            float p[4][4], vv[4][4];
#pragma unroll
            for (int i = 0; i < 4; i++)
                *(float4*)p[i] = *(const float4*)(KtPs + (r0 + i) * 64 + jb * 4);
#pragma unroll
            for (int jj = 0; jj < 4; jj++)
                *(float4*)vv[jj] = *(const float4*)(Vs + (jb * 4 + jj) * 64 + c0);
#pragma unroll
            for (int i = 0; i < 4; i++)
#pragma unroll
                for (int jj = 0; jj < 4; jj++)
#pragma unroll
                    for (int j = 0; j < 4; j++)
                        o[i][j] = fmaf(p[i][jj], vv[jj][j], o[i][j]);
        }
    }

    // Epilogue: out[b, q0+r, h*64 + c] = o / l
    float* op = g_ao + ((size_t)(b * LL + q0)) * DD + h * DHH;
#pragma unroll
    for (int i = 0; i < 4; i++) {
        float inv = 1.0f / l_r[i];
        float4 ov = make_float4(o[i][0] * inv, o[i][1] * inv,
                                o[i][2] * inv, o[i][3] * inv);
        *(float4*)(op + (size_t)(r0 + i) * DD + c0) = ov;
    }
}

// ---------------------------------------------------------------------------
extern "C" void kernel_launch(void* const* d_in, const int* in_sizes, int n_in,
                              void* d_out, int out_size)
{
    (void)in_sizes; (void)n_in; (void)out_size;
    const float* x  = (const float*)d_in[0];
    // d_in[1] = causal_mask — causal is handled analytically, tensor ignored.
    const float* wq = (const float*)d_in[2];
    const float* bq = (const float*)d_in[3];
    const float* wk = (const float*)d_in[4];
    const float* bk = (const float*)d_in[5];
    const float* wv = (const float*)d_in[6];
    const float* bv = (const float*)d_in[7];
    const float* wo = (const float*)d_in[8];
    const float* bo = (const float*)d_in[9];
    float* out = (float*)d_out;

    dim3 gQKV(DD / 128, (BB * LL) / 128, 3);     // 8 x 32 x 3
    sgemm_qkv<<<gQKV, 256>>>(x, wq, bq, wk, bk, wv, bv);

    dim3 gA(LL / 64, BB * HH);                    // 32 x 32
    attn_kernel<<<gA, 256>>>();

    dim3 gO(DD / 128, (BB * LL) / 128);           // 8 x 32
    sgemm_out<<<gO, 256>>>(wo, bo, out);
}

// round 3
// speedup vs baseline: 1.4589x; 1.4589x over previous
#include <cuda_runtime.h>
#include <cuda_bf16.h>
#include <cstdint>
#include <math.h>

#define BB 2
#define LL 2048
#define DD 1024
#define HH 16
#define DHH 64
#define MM (BB * LL)   // 4096

// ---------------------------------------------------------------------------
// Scratch (__device__ globals: allocation-free rule)
// ---------------------------------------------------------------------------
__device__ float g_q[MM * DD];
__device__ float g_k[MM * DD];
__device__ float g_v[MM * DD];
__device__ float g_ao[MM * DD];

__device__ __nv_bfloat16 g_xhi[MM * DD];
__device__ __nv_bfloat16 g_xlo[MM * DD];
__device__ __nv_bfloat16 g_aohi[MM * DD];
__device__ __nv_bfloat16 g_aolo[MM * DD];
// transposed weights: [which][n][k]
__device__ __nv_bfloat16 g_wthi[4][DD * DD];
__device__ __nv_bfloat16 g_wtlo[4][DD * DD];

// ---------------------------------------------------------------------------
// Portable PTX helpers (sm_80+; NO tcgen05 — harness builds plain sm_103)
// ---------------------------------------------------------------------------
__device__ __forceinline__ uint32_t smem_to_u32(const void* p) {
    uint32_t a;
    asm("{ .reg .u64 t; cvta.to.shared.u64 t, %1; cvt.u32.u64 %0, t; }"
        : "=r"(a) : "l"(p));
    return a;
}
__device__ __forceinline__ void cpasync16(uint32_t s, const void* g) {
    asm volatile("cp.async.cg.shared.global [%0], [%1], 16;" :: "r"(s), "l"(g));
}
__device__ __forceinline__ void cpcommit() {
    asm volatile("cp.async.commit_group;" ::: "memory");
}
template <int N>
__device__ __forceinline__ void cpwait() {
    asm volatile("cp.async.wait_group %0;" :: "n"(N) : "memory");
}
__device__ __forceinline__ void ldsm4(uint32_t* r, uint32_t addr) {
    asm volatile("ldmatrix.sync.aligned.m8n8.x4.shared.b16 {%0,%1,%2,%3}, [%4];"
                 : "=r"(r[0]), "=r"(r[1]), "=r"(r[2]), "=r"(r[3]) : "r"(addr));
}
__device__ __forceinline__ void mma_bf16(float* d, const uint32_t* a, const uint32_t* b) {
    asm volatile(
        "mma.sync.aligned.m16n8k16.row.col.f32.bf16.bf16.f32 "
        "{%0,%1,%2,%3}, {%4,%5,%6,%7}, {%8,%9}, {%0,%1,%2,%3};"
        : "+f"(d[0]), "+f"(d[1]), "+f"(d[2]), "+f"(d[3])
        : "r"(a[0]), "r"(a[1]), "r"(a[2]), "r"(a[3]), "r"(b[0]), "r"(b[1]));
}

// ---------------------------------------------------------------------------
// Prep kernels: fp32 -> (hi, lo) bf16 split
// ---------------------------------------------------------------------------
__global__ __launch_bounds__(256) void split_kernel(const float* __restrict__ xin, int which)
{
    const float* in = (which == 0) ? xin : g_ao;
    __nv_bfloat16* hi = (which == 0) ? g_xhi : g_aohi;
    __nv_bfloat16* lo = (which == 0) ? g_xlo : g_aolo;
    int i = blockIdx.x * blockDim.x + threadIdx.x;
    float4 v = ((const float4*)in)[i];
    __nv_bfloat16 h0 = __float2bfloat16(v.x);
    __nv_bfloat16 h1 = __float2bfloat16(v.y);
    __nv_bfloat16 h2 = __float2bfloat16(v.z);
    __nv_bfloat16 h3 = __float2bfloat16(v.w);
    __nv_bfloat162* hp = (__nv_bfloat162*)hi;
    __nv_bfloat162* lp = (__nv_bfloat162*)lo;
    hp[2 * i]     = __nv_bfloat162(h0, h1);
    hp[2 * i + 1] = __nv_bfloat162(h2, h3);
    lp[2 * i]     = __nv_bfloat162(__float2bfloat16(v.x - __bfloat162float(h0)),
                                   __float2bfloat16(v.y - __bfloat162float(h1)));
    lp[2 * i + 1] = __nv_bfloat162(__float2bfloat16(v.z - __bfloat162float(h2)),
                                   __float2bfloat16(v.w - __bfloat162float(h3)));
}

// Transpose + split weights: W[K][N] -> Wt[n][k] hi/lo
__global__ __launch_bounds__(1024) void wsplit_kernel(const float* __restrict__ wq,
                                                      const float* __restrict__ wk,
                                                      const float* __restrict__ wv,
                                                      const float* __restrict__ wo)
{
    __shared__ float t[32][33];
    int which = blockIdx.z;
    const float* w = (which == 0) ? wq : (which == 1) ? wk : (which == 2) ? wv : wo;
    int kk = blockIdx.y * 32 + threadIdx.y;
    int nn = blockIdx.x * 32 + threadIdx.x;
    t[threadIdx.y][threadIdx.x] = w[kk * DD + nn];
    __syncthreads();
    int on = blockIdx.x * 32 + threadIdx.y;
    int ok = blockIdx.y * 32 + threadIdx.x;
    float v = t[threadIdx.x][threadIdx.y];
    __nv_bfloat16 h = __float2bfloat16(v);
    g_wthi[which][on * DD + ok] = h;
    g_wtlo[which][on * DD + ok] = __float2bfloat16(v - __bfloat162float(h));
}

// ---------------------------------------------------------------------------
// Split-bf16 HMMA GEMM: C[128,128 tile] = A @ Wt^T + bias
// 256 thr, warp grid 2(m)x4(n), warp tile 64x32, BK=32 double-buffered cp.async.
// smem pitch 40 elems (80B) -> conflict-free ldmatrix.
// ---------------------------------------------------------------------------
#define BK 32
#define APITCH 40
#define STAGE_BYTES (128 * APITCH * 2)              // 10240
#define GEMM_SMEM_BYTES (8 * STAGE_BYTES)           // 81920: 4 bufs x 2 stages

__device__ __forceinline__ void load_stage(uint32_t sbase, int stage,
                                           const __nv_bfloat16* __restrict__ Ahi,
                                           const __nv_bfloat16* __restrict__ Alo,
                                           const __nv_bfloat16* __restrict__ Bhi,
                                           const __nv_bfloat16* __restrict__ Blo,
                                           int m0, int n0, int k0, int tid)
{
    uint32_t so = sbase + stage * STAGE_BYTES;
#pragma unroll
    for (int j = 0; j < 2; j++) {
        int c = tid + (j << 8);                 // 0..511
        int row = c >> 2;                       // 0..127
        int col = (c & 3) << 3;                 // 0,8,16,24 elements
        uint32_t soff = (uint32_t)(row * APITCH + col) * 2;
        size_t ga = (size_t)(m0 + row) * DD + k0 + col;
        size_t gb = (size_t)(n0 + row) * DD + k0 + col;
        cpasync16(so + 0 * STAGE_BYTES + soff, Ahi + ga);
        cpasync16(so + 2 * STAGE_BYTES + soff, Alo + ga);
        cpasync16(so + 4 * STAGE_BYTES + soff, Bhi + gb);
        cpasync16(so + 6 * STAGE_BYTES + soff, Blo + gb);
    }
}

__device__ __forceinline__ void gemm_tc_body(const __nv_bfloat16* __restrict__ Ahi,
                                             const __nv_bfloat16* __restrict__ Alo,
                                             const __nv_bfloat16* __restrict__ Bhi,
                                             const __nv_bfloat16* __restrict__ Blo,
                                             const float* __restrict__ bias,
                                             float* __restrict__ C)
{
    extern __shared__ char smem[];
    const uint32_t sbase = smem_to_u32(smem);

    const int tid = threadIdx.x;
    const int lane = tid & 31;
    const int wid = tid >> 5;
    const int wm = (wid >> 2) * 64;     // 0 or 64
    const int wn = (wid & 3) * 32;      // 0,32,64,96
    const int m0 = blockIdx.y * 128;
    const int n0 = blockIdx.x * 128;

    // Per-lane ldmatrix base offsets (element units, without k/stage):
    // A: row = wm + mt*16 + (lane&15), col = (lane>>4)*8
    const int a_row = wm + (lane & 15);
    const int a_col = (lane >> 4) << 3;
    // B: row = wn + nt2*16 + ((lane>>4)<<3) + (lane&7), col = ((lane>>3)&1)*8
    const int b_row = wn + ((lane >> 4) << 3) + (lane & 7);
    const int b_col = ((lane >> 3) & 1) << 3;

    float acc[4][4][4];
#pragma unroll
    for (int i = 0; i < 4; i++)
#pragma unroll
        for (int j = 0; j < 4; j++)
#pragma unroll
            for (int r = 0; r < 4; r++) acc[i][j][r] = 0.f;

    load_stage(sbase, 0, Ahi, Alo, Bhi, Blo, m0, n0, 0, tid);
    cpcommit();

    const int NT = DD / BK;             // 32
    for (int kt = 0; kt < NT; kt++) {
        if (kt + 1 < NT) {
            load_stage(sbase, (kt + 1) & 1, Ahi, Alo, Bhi, Blo, m0, n0, (kt + 1) * BK, tid);
            cpcommit();
            cpwait<1>();
        } else {
            cpwait<0>();
        }
        __syncthreads();

        const uint32_t st = sbase + (kt & 1) * STAGE_BYTES;
#pragma unroll
        for (int ks = 0; ks < 2; ks++) {
            const int kofs = ks * 16;
            uint32_t ah[4][4], al[4][4], bh[2][4], bl[2][4];
#pragma unroll
            for (int mt = 0; mt < 4; mt++) {
                uint32_t off = (uint32_t)((a_row + mt * 16) * APITCH + kofs + a_col) * 2;
                ldsm4(ah[mt], st + 0 * STAGE_BYTES + off);
            }
#pragma unroll
            for (int nt2 = 0; nt2 < 2; nt2++) {
                uint32_t off = (uint32_t)((b_row + nt2 * 16) * APITCH + kofs + b_col) * 2;
                ldsm4(bh[nt2], st + 4 * STAGE_BYTES + off);
            }
            // pass 1: hi * hi
#pragma unroll
            for (int mt = 0; mt < 4; mt++)
#pragma unroll
                for (int nt = 0; nt < 4; nt++)
                    mma_bf16(acc[mt][nt], ah[mt], &bh[nt >> 1][(nt & 1) * 2]);
            // pass 2: lo * hi
#pragma unroll
            for (int mt = 0; mt < 4; mt++) {
                uint32_t off = (uint32_t)((a_row + mt * 16) * APITCH + kofs + a_col) * 2;
                ldsm4(al[mt], st + 2 * STAGE_BYTES + off);
            }
#pragma unroll
            for (int mt = 0; mt < 4; mt++)
#pragma unroll
                for (int nt = 0; nt < 4; nt++)
                    mma_bf16(acc[mt][nt], al[mt], &bh[nt >> 1][(nt & 1) * 2]);
            // pass 3: hi * lo
#pragma unroll
            for (int nt2 = 0; nt2 < 2; nt2++) {
                uint32_t off = (uint32_t)((b_row + nt2 * 16) * APITCH + kofs + b_col) * 2;
                ldsm4(bl[nt2], st + 6 * STAGE_BYTES + off);
            }
#pragma unroll
            for (int mt = 0; mt < 4; mt++)
#pragma unroll
                for (int nt = 0; nt < 4; nt++)
                    mma_bf16(acc[mt][nt], ah[mt], &bl[nt >> 1][(nt & 1) * 2]);
        }
        __syncthreads();
    }

    // Epilogue: c0,c1 -> (row, col..col+1); c2,c3 -> (row+8, col..col+1)
#pragma unroll
    for (int mt = 0; mt < 4; mt++) {
        int row = m0 + wm + mt * 16 + (lane >> 2);
#pragma unroll
        for (int nt = 0; nt < 4; nt++) {
            int col = n0 + wn + nt * 8 + 2 * (lane & 3);
            float b0 = bias[col], b1 = bias[col + 1];
            float* p = C + (size_t)row * DD + col;
            *(float2*)p = make_float2(acc[mt][nt][0] + b0, acc[mt][nt][1] + b1);
            *(float2*)(p + 8 * DD) = make_float2(acc[mt][nt][2] + b0, acc[mt][nt][3] + b1);
        }
    }
}

__global__ __launch_bounds__(256, 2)
void gemm_qkv_tc(const float* __restrict__ bq, const float* __restrict__ bk,
                 const float* __restrict__ bv)
{
    const int z = blockIdx.z;
    const float* bias = (z == 0) ? bq : (z == 1) ? bk : bv;
    float* C = (z == 0) ? g_q : (z == 1) ? g_k : g_v;
    gemm_tc_body(g_xhi, g_xlo, g_wthi[z], g_wtlo[z], bias, C);
}

__global__ __launch_bounds__(256, 2)
void gemm_out_tc(const float* __restrict__ bo, float* __restrict__ out)
{
    gemm_tc_body(g_aohi, g_aolo, g_wthi[3], g_wtlo[3], bo, out);
}

// ---------------------------------------------------------------------------
// Flash attention, fp32, causal (unchanged from R1)
// ---------------------------------------------------------------------------
__global__ __launch_bounds__(256) void attn_kernel()
{
    __shared__ __align__(16) float Qt[64 * 64];
    __shared__ __align__(16) float KtPs[64 * 64];
    __shared__ __align__(16) float Vs[64 * 64];

    const int tid = threadIdx.x;
    const int bh = blockIdx.y;
    const int b = bh >> 4;
    const int h = bh & 15;
    const int q0 = blockIdx.x << 6;

    const float* qp = g_q + ((size_t)(b * LL + q0)) * DD + h * DHH;
    const float* kp = g_k + ((size_t)(b * LL)) * DD + h * DHH;
    const float* vp = g_v + ((size_t)(b * LL)) * DD + h * DHH;

#pragma unroll
    for (int it = 0; it < 4; it++) {
        int idx = tid + (it << 8);
        int r = idx >> 4;
        int c = (idx & 15) << 2;
        float4 t = *(const float4*)(qp + (size_t)r * DD + c);
        Qt[(c + 0) * 64 + r] = t.x * 0.125f;
        Qt[(c + 1) * 64 + r] = t.y * 0.125f;
        Qt[(c + 2) * 64 + r] = t.z * 0.125f;
        Qt[(c + 3) * 64 + r] = t.w * 0.125f;
    }

    const int rg = tid >> 4;
    const int cg = tid & 15;
    const int r0 = rg << 2;
    const int c0 = cg << 2;

    float m_r[4], l_r[4], o[4][4];
#pragma unroll
    for (int i = 0; i < 4; i++) {
        m_r[i] = -1e30f;
        l_r[i] = 0.f;
#pragma unroll
        for (int j = 0; j < 4; j++) o[i][j] = 0.f;
    }

    const int ntiles = (q0 >> 6) + 1;
    for (int t = 0; t < ntiles; t++) {
        const int k0 = t << 6;
        __syncthreads();

#pragma unroll
        for (int it = 0; it < 4; it++) {
            int idx = tid + (it << 8);
            int r = idx >> 4;
            int c = (idx & 15) << 2;
            float4 kv = *(const float4*)(kp + (size_t)(k0 + r) * DD + c);
            KtPs[(c + 0) * 64 + r] = kv.x;
            KtPs[(c + 1) * 64 + r] = kv.y;
            KtPs[(c + 2) * 64 + r] = kv.z;
            KtPs[(c + 3) * 64 + r] = kv.w;
            *(float4*)(Vs + r * 64 + c) =
                *(const float4*)(vp + (size_t)(k0 + r) * DD + c);
        }
        __syncthreads();

        float s[4][4];
#pragma unroll
        for (int i = 0; i < 4; i++)
#pragma unroll
            for (int j = 0; j < 4; j++) s[i][j] = 0.f;

#pragma unroll
        for (int d = 0; d < 64; d++) {
            float a[4], bb[4];
            *(float4*)a  = *(const float4*)(Qt + d * 64 + r0);
            *(float4*)bb = *(const float4*)(KtPs + d * 64 + c0);
#pragma unroll
            for (int i = 0; i < 4; i++)
#pragma unroll
                for (int j = 0; j < 4; j++)
                    s[i][j] = fmaf(a[i], bb[j], s[i][j]);
        }

        if (k0 == q0) {
#pragma unroll
            for (int i = 0; i < 4; i++)
#pragma unroll
                for (int j = 0; j < 4; j++)
                    if (c0 + j > r0 + i) s[i][j] = -1e30f;
        }

#pragma unroll
        for (int i = 0; i < 4; i++) {
            float mx = fmaxf(fmaxf(s[i][0], s[i][1]), fmaxf(s[i][2], s[i][3]));
            mx = fmaxf(mx, __shfl_xor_sync(0xffffffffu, mx, 1));
            mx = fmaxf(mx, __shfl_xor_sync(0xffffffffu, mx, 2));
            mx = fmaxf(mx, __shfl_xor_sync(0xffffffffu, mx, 4));
            mx = fmaxf(mx, __shfl_xor_sync(0xffffffffu, mx, 8));
            float m_new = fmaxf(m_r[i], mx);
            float alpha = __expf(m_r[i] - m_new);
            m_r[i] = m_new;
            float rs = 0.f;
#pragma unroll
            for (int j = 0; j < 4; j++) {
                float p = __expf(s[i][j] - m_new);
                s[i][j] = p;
                rs += p;
            }
            rs += __shfl_xor_sync(0xffffffffu, rs, 1);
            rs += __shfl_xor_sync(0xffffffffu, rs, 2);
            rs += __shfl_xor_sync(0xffffffffu, rs, 4);
            rs += __shfl_xor_sync(0xffffffffu, rs, 8);
            l_r[i] = l_r[i] * alpha + rs;
#pragma unroll
            for (int j = 0; j < 4; j++) o[i][j] *= alpha;
        }

        __syncthreads();
#pragma unroll
        for (int i = 0; i < 4; i++)
            *(float4*)(KtPs + (r0 + i) * 64 + c0) =
                make_float4(s[i][0], s[i][1], s[i][2], s[i][3]);
        __syncthreads();

#pragma unroll
        for (int jb = 0; jb < 16; jb++) {
            float p[4][4], vv[4][4];
#pragma unroll
            for (int i = 0; i < 4; i++)
                *(float4*)p[i] = *(const float4*)(KtPs + (r0 + i) * 64 + jb * 4);
#pragma unroll
            for (int jj = 0; jj < 4; jj++)
                *(float4*)vv[jj] = *(const float4*)(Vs + (jb * 4 + jj) * 64 + c0);
#pragma unroll
            for (int i = 0; i < 4; i++)
#pragma unroll
                for (int jj = 0; jj < 4; jj++)
#pragma unroll
                    for (int j = 0; j < 4; j++)
                        o[i][j] = fmaf(p[i][jj], vv[jj][j], o[i][j]);
        }
    }

    float* op = g_ao + ((size_t)(b * LL + q0)) * DD + h * DHH;
#pragma unroll
    for (int i = 0; i < 4; i++) {
        float inv = 1.0f / l_r[i];
        float4 ov = make_float4(o[i][0] * inv, o[i][1] * inv,
                                o[i][2] * inv, o[i][3] * inv);
        *(float4*)(op + (size_t)(r0 + i) * DD + c0) = ov;
    }
}

// ---------------------------------------------------------------------------
extern "C" void kernel_launch(void* const* d_in, const int* in_sizes, int n_in,
                              void* d_out, int out_size)
{
    (void)in_sizes; (void)n_in; (void)out_size;
    const float* x  = (const float*)d_in[0];
    const float* wq = (const float*)d_in[2];
    const float* bq = (const float*)d_in[3];
    const float* wk = (const float*)d_in[4];
    const float* bk = (const float*)d_in[5];
    const float* wv = (const float*)d_in[6];
    const float* bv = (const float*)d_in[7];
    const float* wo = (const float*)d_in[8];
    const float* bo = (const float*)d_in[9];
    float* out = (float*)d_out;

    cudaFuncSetAttribute(gemm_qkv_tc, cudaFuncAttributeMaxDynamicSharedMemorySize,
                         GEMM_SMEM_BYTES);
    cudaFuncSetAttribute(gemm_out_tc, cudaFuncAttributeMaxDynamicSharedMemorySize,
                         GEMM_SMEM_BYTES);

    // 1. split x -> bf16 hi/lo
    split_kernel<<<(MM * DD / 4) / 256, 256>>>(x, 0);
    // 2. transpose+split all 4 weights
    wsplit_kernel<<<dim3(32, 32, 4), dim3(32, 32)>>>(wq, wk, wv, wo);
    // 3. QKV projections (HMMA split-bf16)
    gemm_qkv_tc<<<dim3(DD / 128, MM / 128, 3), 256, GEMM_SMEM_BYTES>>>(bq, bk, bv);
    // 4. attention (SIMT flash, fp32)
    attn_kernel<<<dim3(LL / 64, BB * HH), 256>>>();
    // 5. split attention output
    split_kernel<<<(MM * DD / 4) / 256, 256>>>(nullptr, 1);
    // 6. output projection (HMMA split-bf16)
    gemm_out_tc<<<dim3(DD / 128, MM / 128), 256, GEMM_SMEM_BYTES>>>(bo, out);
}

// round 4
// speedup vs baseline: 2.9443x; 2.0182x over previous
#include <cuda_runtime.h>
#include <cuda_bf16.h>
#include <cuda_fp16.h>
#include <cstdint>
#include <math.h>

#define BB 2
#define LL 2048
#define DD 1024
#define HH 16
#define DHH 64
#define MM (BB * LL)   // 4096
#define L2E 1.4426950408889634f

// ---------------------------------------------------------------------------
// Scratch (__device__ globals: allocation-free rule)
// ---------------------------------------------------------------------------
__device__ float g_ao[MM * DD];

__device__ __nv_bfloat16 g_xhi[MM * DD];
__device__ __nv_bfloat16 g_xlo[MM * DD];
__device__ __nv_bfloat16 g_aohi[MM * DD];
__device__ __nv_bfloat16 g_aolo[MM * DD];
__device__ __nv_bfloat16 g_wthi[4][DD * DD];
__device__ __nv_bfloat16 g_wtlo[4][DD * DD];

// attention operands, pre-split by the projection epilogues
__device__ __nv_bfloat16 g_qhi[MM * DD];  // pre-scaled by 0.125
__device__ __nv_bfloat16 g_qlo[MM * DD];
__device__ __nv_bfloat16 g_khi[MM * DD];
__device__ __nv_bfloat16 g_klo[MM * DD];
__device__ __half        g_vhi[MM * DD];
__device__ __half        g_vlo[MM * DD];

// ---------------------------------------------------------------------------
// PTX helpers (portable sm_80+ subset; plain sm_103 target — no tcgen05)
// ---------------------------------------------------------------------------
__device__ __forceinline__ uint32_t smem_to_u32(const void* p) {
    uint32_t a;
    asm("{ .reg .u64 t; cvta.to.shared.u64 t, %1; cvt.u32.u64 %0, t; }"
        : "=r"(a) : "l"(p));
    return a;
}
__device__ __forceinline__ void cpasync16(uint32_t s, const void* g) {
    asm volatile("cp.async.cg.shared.global [%0], [%1], 16;" :: "r"(s), "l"(g));
}
__device__ __forceinline__ void cpcommit() {
    asm volatile("cp.async.commit_group;" ::: "memory");
}
template <int N>
__device__ __forceinline__ void cpwait() {
    asm volatile("cp.async.wait_group %0;" :: "n"(N) : "memory");
}
__device__ __forceinline__ void ldsm4(uint32_t* r, uint32_t addr) {
    asm volatile("ldmatrix.sync.aligned.m8n8.x4.shared.b16 {%0,%1,%2,%3}, [%4];"
                 : "=r"(r[0]), "=r"(r[1]), "=r"(r[2]), "=r"(r[3]) : "r"(addr));
}
__device__ __forceinline__ void ldsm4t(uint32_t* r, uint32_t addr) {
    asm volatile("ldmatrix.sync.aligned.m8n8.x4.trans.shared.b16 {%0,%1,%2,%3}, [%4];"
                 : "=r"(r[0]), "=r"(r[1]), "=r"(r[2]), "=r"(r[3]) : "r"(addr));
}
__device__ __forceinline__ void mma_bf16(float* d, const uint32_t* a, const uint32_t* b) {
    asm volatile(
        "mma.sync.aligned.m16n8k16.row.col.f32.bf16.bf16.f32 "
        "{%0,%1,%2,%3}, {%4,%5,%6,%7}, {%8,%9}, {%0,%1,%2,%3};"
        : "+f"(d[0]), "+f"(d[1]), "+f"(d[2]), "+f"(d[3])
        : "r"(a[0]), "r"(a[1]), "r"(a[2]), "r"(a[3]), "r"(b[0]), "r"(b[1]));
}
__device__ __forceinline__ void mma_f16(float* d, const uint32_t* a, const uint32_t* b) {
    asm volatile(
        "mma.sync.aligned.m16n8k16.row.col.f32.f16.f16.f32 "
        "{%0,%1,%2,%3}, {%4,%5,%6,%7}, {%8,%9}, {%0,%1,%2,%3};"
        : "+f"(d[0]), "+f"(d[1]), "+f"(d[2]), "+f"(d[3])
        : "r"(a[0]), "r"(a[1]), "r"(a[2]), "r"(a[3]), "r"(b[0]), "r"(b[1]));
}
__device__ __forceinline__ uint32_t cvt_f16x2(float hi, float lo) {
    uint32_t r;
    asm volatile("cvt.rn.f16x2.f32 %0, %1, %2;" : "=r"(r) : "f"(hi), "f"(lo));
    return r;
}
__device__ __forceinline__ uint32_t ex2_f16x2(uint32_t x) {
    uint32_t r;
    asm volatile("ex2.approx.f16x2 %0, %1;" : "=r"(r) : "r"(x));
    return r;
}

// ---------------------------------------------------------------------------
// Prep kernels: fp32 -> (hi, lo) bf16 split
// ---------------------------------------------------------------------------
__global__ __launch_bounds__(256) void split_kernel(const float* __restrict__ xin, int which)
{
    const float* in = (which == 0) ? xin : g_ao;
    __nv_bfloat16* hi = (which == 0) ? g_xhi : g_aohi;
    __nv_bfloat16* lo = (which == 0) ? g_xlo : g_aolo;
    int i = blockIdx.x * blockDim.x + threadIdx.x;
    float4 v = ((const float4*)in)[i];
    __nv_bfloat16 h0 = __float2bfloat16(v.x);
    __nv_bfloat16 h1 = __float2bfloat16(v.y);
    __nv_bfloat16 h2 = __float2bfloat16(v.z);
    __nv_bfloat16 h3 = __float2bfloat16(v.w);
    __nv_bfloat162* hp = (__nv_bfloat162*)hi;
    __nv_bfloat162* lp = (__nv_bfloat162*)lo;
    hp[2 * i]     = __nv_bfloat162(h0, h1);
    hp[2 * i + 1] = __nv_bfloat162(h2, h3);
    lp[2 * i]     = __nv_bfloat162(__float2bfloat16(v.x - __bfloat162float(h0)),
                                   __float2bfloat16(v.y - __bfloat162float(h1)));
    lp[2 * i + 1] = __nv_bfloat162(__float2bfloat16(v.z - __bfloat162float(h2)),
                                   __float2bfloat16(v.w - __bfloat162float(h3)));
}

__global__ __launch_bounds__(1024) void wsplit_kernel(const float* __restrict__ wq,
                                                      const float* __restrict__ wk,
                                                      const float* __restrict__ wv,
                                                      const float* __restrict__ wo)
{
    __shared__ float t[32][33];
    int which = blockIdx.z;
    const float* w = (which == 0) ? wq : (which == 1) ? wk : (which == 2) ? wv : wo;
    int kk = blockIdx.y * 32 + threadIdx.y;
    int nn = blockIdx.x * 32 + threadIdx.x;
    t[threadIdx.y][threadIdx.x] = w[kk * DD + nn];
    __syncthreads();
    int on = blockIdx.x * 32 + threadIdx.y;
    int ok = blockIdx.y * 32 + threadIdx.x;
    float v = t[threadIdx.x][threadIdx.y];
    __nv_bfloat16 h = __float2bfloat16(v);
    g_wthi[which][on * DD + ok] = h;
    g_wtlo[which][on * DD + ok] = __float2bfloat16(v - __bfloat162float(h));
}

// ---------------------------------------------------------------------------
// Split-bf16 HMMA GEMM with mode-dependent epilogue.
// mode 0: fp32 C; mode 1: bf16 split *0.125 (Q); mode 2: bf16 split (K);
// mode 3: f16 split (V).
// ---------------------------------------------------------------------------
#define BK 32
#define APITCH 40
#define STAGE_BYTES (128 * APITCH * 2)
#define GEMM_SMEM_BYTES (8 * STAGE_BYTES)

__device__ __forceinline__ void load_stage(uint32_t sbase, int stage,
                                           const __nv_bfloat16* __restrict__ Ahi,
                                           const __nv_bfloat16* __restrict__ Alo,
                                           const __nv_bfloat16* __restrict__ Bhi,
                                           const __nv_bfloat16* __restrict__ Blo,
                                           int m0, int n0, int k0, int tid)
{
    uint32_t so = sbase + stage * STAGE_BYTES;
#pragma unroll
    for (int j = 0; j < 2; j++) {
        int c = tid + (j << 8);
        int row = c >> 2;
        int col = (c & 3) << 3;
        uint32_t soff = (uint32_t)(row * APITCH + col) * 2;
        size_t ga = (size_t)(m0 + row) * DD + k0 + col;
        size_t gb = (size_t)(n0 + row) * DD + k0 + col;
        cpasync16(so + 0 * STAGE_BYTES + soff, Ahi + ga);
        cpasync16(so + 2 * STAGE_BYTES + soff, Alo + ga);
        cpasync16(so + 4 * STAGE_BYTES + soff, Bhi + gb);
        cpasync16(so + 6 * STAGE_BYTES + soff, Blo + gb);
    }
}

__device__ __forceinline__ void gemm_tc_body(const __nv_bfloat16* __restrict__ Ahi,
                                             const __nv_bfloat16* __restrict__ Alo,
                                             const __nv_bfloat16* __restrict__ Bhi,
                                             const __nv_bfloat16* __restrict__ Blo,
                                             const float* __restrict__ bias,
                                             float* __restrict__ C,
                                             int mode, void* oHi, void* oLo)
{
    extern __shared__ char smem[];
    const uint32_t sbase = smem_to_u32(smem);

    const int tid = threadIdx.x;
    const int lane = tid & 31;
    const int wid = tid >> 5;
    const int wm = (wid >> 2) * 64;
    const int wn = (wid & 3) * 32;
    const int m0 = blockIdx.y * 128;
    const int n0 = blockIdx.x * 128;

    const int a_row = wm + (lane & 15);
    const int a_col = (lane >> 4) << 3;
    const int b_row = wn + ((lane >> 4) << 3) + (lane & 7);
    const int b_col = ((lane >> 3) & 1) << 3;

    float acc[4][4][4];
#pragma unroll
    for (int i = 0; i < 4; i++)
#pragma unroll
        for (int j = 0; j < 4; j++)
#pragma unroll
            for (int r = 0; r < 4; r++) acc[i][j][r] = 0.f;

    load_stage(sbase, 0, Ahi, Alo, Bhi, Blo, m0, n0, 0, tid);
    cpcommit();

    const int NT = DD / BK;
    for (int kt = 0; kt < NT; kt++) {
        if (kt + 1 < NT) {
            load_stage(sbase, (kt + 1) & 1, Ahi, Alo, Bhi, Blo, m0, n0, (kt + 1) * BK, tid);
            cpcommit();
            cpwait<1>();
        } else {
            cpwait<0>();
        }
        __syncthreads();

        const uint32_t st = sbase + (kt & 1) * STAGE_BYTES;
#pragma unroll
        for (int ks = 0; ks < 2; ks++) {
            const int kofs = ks * 16;
            uint32_t ah[4][4], al[4][4], bh[2][4], bl[2][4];
#pragma unroll
            for (int mt = 0; mt < 4; mt++) {
                uint32_t off = (uint32_t)((a_row + mt * 16) * APITCH + kofs + a_col) * 2;
                ldsm4(ah[mt], st + 0 * STAGE_BYTES + off);
            }
#pragma unroll
            for (int nt2 = 0; nt2 < 2; nt2++) {
                uint32_t off = (uint32_t)((b_row + nt2 * 16) * APITCH + kofs + b_col) * 2;
                ldsm4(bh[nt2], st + 4 * STAGE_BYTES + off);
            }
#pragma unroll
            for (int mt = 0; mt < 4; mt++)
#pragma unroll
                for (int nt = 0; nt < 4; nt++)
                    mma_bf16(acc[mt][nt], ah[mt], &bh[nt >> 1][(nt & 1) * 2]);
#pragma unroll
            for (int mt = 0; mt < 4; mt++) {
                uint32_t off = (uint32_t)((a_row + mt * 16) * APITCH + kofs + a_col) * 2;
                ldsm4(al[mt], st + 2 * STAGE_BYTES + off);
            }
#pragma unroll
            for (int mt = 0; mt < 4; mt++)
#pragma unroll
                for (int nt = 0; nt < 4; nt++)
                    mma_bf16(acc[mt][nt], al[mt], &bh[nt >> 1][(nt & 1) * 2]);
#pragma unroll
            for (int nt2 = 0; nt2 < 2; nt2++) {
                uint32_t off = (uint32_t)((b_row + nt2 * 16) * APITCH + kofs + b_col) * 2;
                ldsm4(bl[nt2], st + 6 * STAGE_BYTES + off);
            }
#pragma unroll
            for (int mt = 0; mt < 4; mt++)
#pragma unroll
                for (int nt = 0; nt < 4; nt++)
                    mma_bf16(acc[mt][nt], ah[mt], &bl[nt >> 1][(nt & 1) * 2]);
        }
        __syncthreads();
    }

    const float sc = (mode == 1) ? 0.125f : 1.0f;
#pragma unroll
    for (int mt = 0; mt < 4; mt++) {
        int row = m0 + wm + mt * 16 + (lane >> 2);
#pragma unroll
        for (int nt = 0; nt < 4; nt++) {
            int col = n0 + wn + nt * 8 + 2 * (lane & 3);
            float b0 = bias[col], b1 = bias[col + 1];
            float v0 = acc[mt][nt][0] + b0, v1 = acc[mt][nt][1] + b1;
            float v2 = acc[mt][nt][2] + b0, v3 = acc[mt][nt][3] + b1;
            size_t off0 = (size_t)row * DD + col;
            size_t off1 = (size_t)(row + 8) * DD + col;
            if (mode == 0) {
                *(float2*)(C + off0) = make_float2(v0, v1);
                *(float2*)(C + off1) = make_float2(v2, v3);
            } else if (mode <= 2) {
                v0 *= sc; v1 *= sc; v2 *= sc; v3 *= sc;
                __nv_bfloat16 h0 = __float2bfloat16(v0), h1 = __float2bfloat16(v1);
                __nv_bfloat16 h2 = __float2bfloat16(v2), h3 = __float2bfloat16(v3);
                __nv_bfloat16* Hi = (__nv_bfloat16*)oHi;
                __nv_bfloat16* Lo = (__nv_bfloat16*)oLo;
                *(__nv_bfloat162*)(Hi + off0) = __nv_bfloat162(h0, h1);
                *(__nv_bfloat162*)(Hi + off1) = __nv_bfloat162(h2, h3);
                *(__nv_bfloat162*)(Lo + off0) =
                    __nv_bfloat162(__float2bfloat16(v0 - __bfloat162float(h0)),
                                   __float2bfloat16(v1 - __bfloat162float(h1)));
                *(__nv_bfloat162*)(Lo + off1) =
                    __nv_bfloat162(__float2bfloat16(v2 - __bfloat162float(h2)),
                                   __float2bfloat16(v3 - __bfloat162float(h3)));
            } else {
                __half h0 = __float2half_rn(v0), h1 = __float2half_rn(v1);
                __half h2 = __float2half_rn(v2), h3 = __float2half_rn(v3);
                __half* Hi = (__half*)oHi;
                __half* Lo = (__half*)oLo;
                *(__half2*)(Hi + off0) = __half2(h0, h1);
                *(__half2*)(Hi + off1) = __half2(h2, h3);
                *(__half2*)(Lo + off0) = __half2(__float2half_rn(v0 - __half2float(h0)),
                                                 __float2half_rn(v1 - __half2float(h1)));
                *(__half2*)(Lo + off1) = __half2(__float2half_rn(v2 - __half2float(h2)),
                                                 __float2half_rn(v3 - __half2float(h3)));
            }
        }
    }
}

__global__ __launch_bounds__(256, 2)
void gemm_qkv_tc(const float* __restrict__ bq, const float* __restrict__ bk,
                 const float* __restrict__ bv)
{
    const int z = blockIdx.z;
    if (z == 0)
        gemm_tc_body(g_xhi, g_xlo, g_wthi[0], g_wtlo[0], bq, nullptr, 1, g_qhi, g_qlo);
    else if (z == 1)
        gemm_tc_body(g_xhi, g_xlo, g_wthi[1], g_wtlo[1], bk, nullptr, 2, g_khi, g_klo);
    else
        gemm_tc_body(g_xhi, g_xlo, g_wthi[2], g_wtlo[2], bv, nullptr, 3, g_vhi, g_vlo);
}

__global__ __launch_bounds__(256, 2)
void gemm_out_tc(const float* __restrict__ bo, float* __restrict__ out)
{
    gemm_tc_body(g_aohi, g_aolo, g_wthi[3], g_wtlo[3], bo, out, 0, nullptr, nullptr);
}

// ---------------------------------------------------------------------------
// Tensor-core flash attention, causal.
// CTA: 64 q rows, 128 threads (4 warps x 16 rows). Key tiles of 64.
// QK^T: split-bf16 3-pass HMMA. P: f16 via ex2.approx.f16x2.
// PV: f16 HMMA, V split hi/lo (2-pass), ones-column in V col 64 carries l.
// smem: Qh,Ql,Kh,Kl [64][64] bf16 XOR-swizzled (128B rows); Vh,Vl [64][88] f16.
// ---------------------------------------------------------------------------
#define ATT_QH 0
#define ATT_QL 8192
#define ATT_KH 16384
#define ATT_KL 24576
#define ATT_VH 32768
#define ATT_VL 44032
#define ATT_SMEM 55296
#define VPITCH 88

__global__ __launch_bounds__(128, 3) void attn_tc_kernel()
{
    extern __shared__ char sm[];
    const uint32_t sb = smem_to_u32(sm);
    const int tid = threadIdx.x;
    const int lane = tid & 31;
    const int wid = tid >> 5;
    const int bh = blockIdx.y;
    const int b = bh >> 4;
    const int h = bh & 15;
    const int q0 = (int)(gridDim.x - 1 - blockIdx.x) * 64;   // big tiles first

    const size_t tok0 = (size_t)(b * LL);
    const __nv_bfloat16* gqh = g_qhi + (tok0 + q0) * DD + h * 64;
    const __nv_bfloat16* gql = g_qlo + (tok0 + q0) * DD + h * 64;
    const __nv_bfloat16* gkh = g_khi + tok0 * DD + h * 64;
    const __nv_bfloat16* gkl = g_klo + tok0 * DD + h * 64;
    const __half*        gvh = g_vhi + tok0 * DD + h * 64;
    const __half*        gvl = g_vlo + tok0 * DD + h * 64;

    // V pad cols 64..87: zeros, except Vh col 64 = 1.0 (ones column -> l)
    for (int i = tid; i < 64 * 3; i += 128) {
        int r = i / 3, c = i % 3;
        uint32_t off = (uint32_t)(r * VPITCH + 64 + 8 * c) * 2;
        *(uint4*)(sm + ATT_VH + off) = make_uint4(0, 0, 0, 0);
        *(uint4*)(sm + ATT_VL + off) = make_uint4(0, 0, 0, 0);
    }
    __syncthreads();
    if (tid < 64) ((__half*)(sm + ATT_VH))[tid * VPITCH + 64] = __float2half(1.0f);

    // Load Q tile (swizzled)
#pragma unroll
    for (int i = 0; i < 4; i++) {
        int idx = tid + (i << 7);            // 0..511
        int r = idx >> 3, c = idx & 7;
        uint32_t off = 128u * r + 16u * (c ^ (r & 7));
        *(uint4*)(sm + ATT_QH + off) = *(const uint4*)(gqh + (size_t)r * DD + c * 8);
        *(uint4*)(sm + ATT_QL + off) = *(const uint4*)(gql + (size_t)r * DD + c * 8);
    }

    // fragment addressing
    const int arow = 16 * wid + (lane & 15);
    const int ac = lane >> 4;                     // 0/1
    const int asw = arow & 7;
    const int brow_in = ((lane >> 4) << 3) + (lane & 7);  // 0..15
    const int bc = (lane >> 3) & 1;
    const int bsw = brow_in & 7;
    const int vrow_in = (lane & 7) + ((lane >> 3) & 1) * 8;  // 0..15
    const int vnc = (lane >> 4);                  // n chunk 0/1

    float oacc[9][4];
#pragma unroll
    for (int i = 0; i < 9; i++)
#pragma unroll
        for (int j = 0; j < 4; j++) oacc[i][j] = 0.f;
    float m2[2] = {-1e30f, -1e30f};

    const int nk = (q0 >> 6) + 1;
    for (int kt = 0; kt < nk; kt++) {
        const int k0 = kt << 6;
        __syncthreads();
        // Load K (swizzled bf16 hi/lo) and V (f16 hi/lo, pitch 88)
#pragma unroll
        for (int i = 0; i < 4; i++) {
            int idx = tid + (i << 7);
            int r = idx >> 3, c = idx & 7;
            uint32_t offk = 128u * r + 16u * (c ^ (r & 7));
            size_t g = (size_t)(k0 + r) * DD + c * 8;
            *(uint4*)(sm + ATT_KH + offk) = *(const uint4*)(gkh + g);
            *(uint4*)(sm + ATT_KL + offk) = *(const uint4*)(gkl + g);
            uint32_t offv = (uint32_t)(r * VPITCH + c * 8) * 2;
            *(uint4*)(sm + ATT_VH + offv) = *(const uint4*)(gvh + g);
            *(uint4*)(sm + ATT_VL + offv) = *(const uint4*)(gvl + g);
        }
        __syncthreads();

        // ---- S = Q K^T (3-pass split bf16), 16x64 per warp ----
        float sacc[8][4];
#pragma unroll
        for (int i = 0; i < 8; i++)
#pragma unroll
            for (int j = 0; j < 4; j++) sacc[i][j] = 0.f;

#pragma unroll
        for (int ks = 0; ks < 4; ks++) {
            uint32_t qhf[4], qlf[4], kf[4][4];
            uint32_t ca = 16u * (uint32_t)((2 * ks + ac) ^ asw);
            ldsm4(qhf, sb + ATT_QH + 128u * arow + ca);
            ldsm4(qlf, sb + ATT_QL + 128u * arow + ca);
            uint32_t cb = 16u * (uint32_t)((2 * ks + bc) ^ bsw);
#pragma unroll
            for (int np = 0; np < 4; np++)
                ldsm4(kf[np], sb + ATT_KH + 128u * (16 * np + brow_in) + cb);
#pragma unroll
            for (int nt = 0; nt < 8; nt++) {
                mma_bf16(sacc[nt], qhf, &kf[nt >> 1][(nt & 1) * 2]);
                mma_bf16(sacc[nt], qlf, &kf[nt >> 1][(nt & 1) * 2]);
            }
#pragma unroll
            for (int np = 0; np < 4; np++)
                ldsm4(kf[np], sb + ATT_KL + 128u * (16 * np + brow_in) + cb);
#pragma unroll
            for (int nt = 0; nt < 8; nt++)
                mma_bf16(sacc[nt], qhf, &kf[nt >> 1][(nt & 1) * 2]);
        }

        // ---- causal mask (diagonal tile only) ----
        if (kt == nk - 1) {
            const int r0g = 16 * wid + (lane >> 2);
#pragma unroll
            for (int nt = 0; nt < 8; nt++) {
                int kc = 8 * nt + 2 * (lane & 3);
                if (kc > r0g)     sacc[nt][0] = -1e30f;
                if (kc + 1 > r0g) sacc[nt][1] = -1e30f;
                if (kc > r0g + 8)     sacc[nt][2] = -1e30f;
                if (kc + 1 > r0g + 8) sacc[nt][3] = -1e30f;
            }
        }

        // ---- online softmax (log2 domain), P in f16x2 ----
        float mx0 = -1e30f, mx1 = -1e30f;
#pragma unroll
        for (int nt = 0; nt < 8; nt++) {
            mx0 = fmaxf(mx0, fmaxf(sacc[nt][0], sacc[nt][1]));
            mx1 = fmaxf(mx1, fmaxf(sacc[nt][2], sacc[nt][3]));
        }
        mx0 = fmaxf(mx0, __shfl_xor_sync(0xffffffffu, mx0, 1));
        mx0 = fmaxf(mx0, __shfl_xor_sync(0xffffffffu, mx0, 2));
        mx1 = fmaxf(mx1, __shfl_xor_sync(0xffffffffu, mx1, 1));
        mx1 = fmaxf(mx1, __shfl_xor_sync(0xffffffffu, mx1, 2));
        float m2n0 = fmaxf(m2[0], mx0 * L2E);
        float m2n1 = fmaxf(m2[1], mx1 * L2E);
        float al0 = exp2f(m2[0] - m2n0);
        float al1 = exp2f(m2[1] - m2n1);
        m2[0] = m2n0; m2[1] = m2n1;

        uint32_t pf[4][4];
#pragma unroll
        for (int ks = 0; ks < 4; ks++) {
            pf[ks][0] = ex2_f16x2(cvt_f16x2(fmaf(sacc[2*ks][1],   L2E, -m2n0),
                                            fmaf(sacc[2*ks][0],   L2E, -m2n0)));
            pf[ks][1] = ex2_f16x2(cvt_f16x2(fmaf(sacc[2*ks][3],   L2E, -m2n1),
                                            fmaf(sacc[2*ks][2],   L2E, -m2n1)));
            pf[ks][2] = ex2_f16x2(cvt_f16x2(fmaf(sacc[2*ks+1][1], L2E, -m2n0),
                                            fmaf(sacc[2*ks+1][0], L2E, -m2n0)));
            pf[ks][3] = ex2_f16x2(cvt_f16x2(fmaf(sacc[2*ks+1][3], L2E, -m2n1),
                                            fmaf(sacc[2*ks+1][2], L2E, -m2n1)));
        }
#pragma unroll
        for (int nt = 0; nt < 9; nt++) {
            oacc[nt][0] *= al0; oacc[nt][1] *= al0;
            oacc[nt][2] *= al1; oacc[nt][3] *= al1;
        }

        // ---- O += P @ V (f16, V hi/lo 2-pass; n=72 incl. ones column) ----
#pragma unroll
        for (int ks = 0; ks < 4; ks++) {
            const uint32_t vrow = (uint32_t)(16 * ks + vrow_in) * (VPITCH * 2);
#pragma unroll
            for (int np = 0; np < 5; np++) {
                uint32_t vf[4];
                uint32_t voff = vrow + 16u * (uint32_t)(2 * np + vnc);
                ldsm4t(vf, sb + ATT_VH + voff);
                mma_f16(oacc[2 * np], pf[ks], &vf[0]);
                if (np < 4) mma_f16(oacc[2 * np + 1], pf[ks], &vf[2]);
            }
#pragma unroll
            for (int np = 0; np < 5; np++) {
                uint32_t vf[4];
                uint32_t voff = vrow + 16u * (uint32_t)(2 * np + vnc);
                ldsm4t(vf, sb + ATT_VL + voff);
                mma_f16(oacc[2 * np], pf[ks], &vf[0]);
                if (np < 4) mma_f16(oacc[2 * np + 1], pf[ks], &vf[2]);
            }
        }
    }

    // ---- normalize and store ----
    const int src = lane & ~3;
    float l0 = __shfl_sync(0xffffffffu, oacc[8][0], src);
    float l1 = __shfl_sync(0xffffffffu, oacc[8][2], src);
    float i0 = 1.0f / l0;
    float i1 = 1.0f / l1;
    const int row0 = q0 + 16 * wid + (lane >> 2);
    float* base = g_ao + tok0 * DD + h * 64;
#pragma unroll
    for (int nt = 0; nt < 8; nt++) {
        int col = 8 * nt + 2 * (lane & 3);
        *(float2*)(base + (size_t)row0 * DD + col) =
            make_float2(oacc[nt][0] * i0, oacc[nt][1] * i0);
        *(float2*)(base + (size_t)(row0 + 8) * DD + col) =
            make_float2(oacc[nt][2] * i1, oacc[nt][3] * i1);
    }
}

// ---------------------------------------------------------------------------
extern "C" void kernel_launch(void* const* d_in, const int* in_sizes, int n_in,
                              void* d_out, int out_size)
{
    (void)in_sizes; (void)n_in; (void)out_size;
    const float* x  = (const float*)d_in[0];
    const float* wq = (const float*)d_in[2];
    const float* bq = (const float*)d_in[3];
    const float* wk = (const float*)d_in[4];
    const float* bk = (const float*)d_in[5];
    const float* wv = (const float*)d_in[6];
    const float* bv = (const float*)d_in[7];
    const float* wo = (const float*)d_in[8];
    const float* bo = (const float*)d_in[9];
    float* out = (float*)d_out;

    cudaFuncSetAttribute(gemm_qkv_tc, cudaFuncAttributeMaxDynamicSharedMemorySize,
                         GEMM_SMEM_BYTES);
    cudaFuncSetAttribute(gemm_out_tc, cudaFuncAttributeMaxDynamicSharedMemorySize,
                         GEMM_SMEM_BYTES);
    cudaFuncSetAttribute(attn_tc_kernel, cudaFuncAttributeMaxDynamicSharedMemorySize,
                         ATT_SMEM);

    split_kernel<<<(MM * DD / 4) / 256, 256>>>(x, 0);
    wsplit_kernel<<<dim3(32, 32, 4), dim3(32, 32)>>>(wq, wk, wv, wo);
    gemm_qkv_tc<<<dim3(DD / 128, MM / 128, 3), 256, GEMM_SMEM_BYTES>>>(bq, bk, bv);
    attn_tc_kernel<<<dim3(LL / 64, BB * HH), 128, ATT_SMEM>>>();
    split_kernel<<<(MM * DD / 4) / 256, 256>>>(nullptr, 1);
    gemm_out_tc<<<dim3(DD / 128, MM / 128), 256, GEMM_SMEM_BYTES>>>(bo, out);
}